// round 11
// baseline (speedup 1.0000x reference)
#include <cuda_runtime.h>
#include <math.h>
#include <stdint.h>

// B=8, C=128, H=W=256, OC=256, HEADS=4, NB=4, PS=4, OS=16
// q/k: pool16 -> (16,16) -> dw3x3 VALID -> (14,14)=196, per head 49
// v: dw4x4 s4 -> (64,64)=4096, per head 1024
// out tuple: (8,256,64,64) then x (8,128,256,256)

#define OUT0_ELEMS (8*256*64*64)      // 8388608
#define X_ELEMS    (8*128*256*256)    // 67108864

// ---------------- device scratch ----------------
__device__ float g_qpool[8*128*256];
__device__ float g_kpool[8*128*256];
__device__ float g_qf[8*128*196];
__device__ float g_kf[8*128*196];
__device__ float g_vpool[8*128*4096];
__device__ float g_bias[4*128*128];
__device__ float g_sim[8*4*128*128];
__device__ float g_attn[8*128*4096];
__device__ float g_mid[8*128*4096];
__device__ float g_proj[8*256*4096];
__device__ float g_scv[8*256*4096];
__device__ float g_stats[8*4096*4];

__device__ __forceinline__ float warp_max(float v){
#pragma unroll
    for (int o=16;o;o>>=1) v = fmaxf(v, __shfl_xor_sync(0xffffffffu,v,o));
    return v;
}
__device__ __forceinline__ float warp_sum(float v){
#pragma unroll
    for (int o=16;o;o>>=1) v += __shfl_xor_sync(0xffffffffu,v,o);
    return v;
}
__device__ __forceinline__ float gelu_exact(float x){
    return 0.5f*x*(1.0f+erff(x*0.70710678118654752440f));
}

// ---------------- K1: relative position bias ----------------
__global__ void bias_kernel(const float* __restrict__ w1, const float* __restrict__ b1,
                            const float* __restrict__ w2){
    int idx = blockIdx.x*256 + threadIdx.x;          // 0..16383
    int i = idx >> 7, j = idx & 127;
    float rel = (float)(j - i) * (8.0f/127.0f);
    float r2  = copysignf(log2f(fabsf(rel)+1.0f)*(1.0f/3.0f), rel);
    float a0=0.f,a1=0.f,a2=0.f,a3=0.f;
#pragma unroll 8
    for (int m=0;m<64;m++){
        float h = fmaxf(r2*w1[m] + b1[m], 0.0f);
        a0 += h*w2[m]; a1 += h*w2[64+m]; a2 += h*w2[128+m]; a3 += h*w2[192+m];
    }
    g_bias[0*16384+idx] = 1.0f/(1.0f+expf(-a0));
    g_bias[1*16384+idx] = 1.0f/(1.0f+expf(-a1));
    g_bias[2*16384+idx] = 1.0f/(1.0f+expf(-a2));
    g_bias[3*16384+idx] = 1.0f/(1.0f+expf(-a3));
}

// ---------------- K2: fused q/k/v grouped conv + q/k pool16 + v dw4x4-s4 ----------------
// grid (256 tiles, 32 = b*4+g), 256 threads.
// Register tiling: each thread computes 4 channels x 8 pixels for q,k,v
// (96 FMA per k-step vs 5 LDS.128 -> FMA-bound).
__global__ __launch_bounds__(256) void qkv_kernel(
    const float* __restrict__ x,
    const float* __restrict__ qw, const float* __restrict__ qb,
    const float* __restrict__ kw, const float* __restrict__ kb,
    const float* __restrict__ vw, const float* __restrict__ vb,
    const float* __restrict__ vpw, const float* __restrict__ vpb){
    __shared__ float xs[32][256];     // input tile / later reused for v
    __shared__ float wqs[32][32];     // [i][c]
    __shared__ float wks[32][32];
    __shared__ float wvs[32][32];
    int tid = threadIdx.x;
    int bg = blockIdx.y; int b = bg>>2, g = bg&3;
    int tY = blockIdx.x>>4, tX = blockIdx.x&15;

    for (int e=tid; e<1024; e+=256){
        int c = e>>5, i = e&31;
        int gi = (g*32+c)*32 + i;
        wqs[i][c] = qw[gi]; wks[i][c] = kw[gi]; wvs[i][c] = vw[gi];
    }
    {
        const float* xbp = x + (size_t)(b*128 + g*32)*65536
                             + (size_t)(tY*16 + (tid>>4))*256 + tX*16 + (tid&15);
#pragma unroll
        for (int i=0;i<32;i++) xs[i][tid] = xbp[(size_t)i*65536];
    }
    __syncthreads();

    int ch4 = tid >> 5;               // warp id -> channels [ch4*4, ch4*4+4)
    int lane = tid & 31;
    int px0 = lane * 8;               // 8 consecutive pixels (half a row)
    int c0 = ch4 * 4;

    float aq[4][8], ak[4][8], av[4][8];
#pragma unroll
    for (int c=0;c<4;c++){
        float qb0 = qb[g*32 + c0 + c], kb0 = kb[g*32 + c0 + c], vb0 = vb[g*32 + c0 + c];
#pragma unroll
        for (int j=0;j<8;j++){ aq[c][j]=qb0; ak[c][j]=kb0; av[c][j]=vb0; }
    }

#pragma unroll 8
    for (int i=0;i<32;i++){
        float4 xa = *(const float4*)&xs[i][px0];
        float4 xb2 = *(const float4*)&xs[i][px0+4];
        float xv[8] = {xa.x,xa.y,xa.z,xa.w, xb2.x,xb2.y,xb2.z,xb2.w};
        float4 wq4 = *(const float4*)&wqs[i][c0];
        float4 wk4 = *(const float4*)&wks[i][c0];
        float4 wv4 = *(const float4*)&wvs[i][c0];
        float wqv[4]={wq4.x,wq4.y,wq4.z,wq4.w};
        float wkv[4]={wk4.x,wk4.y,wk4.z,wk4.w};
        float wvv[4]={wv4.x,wv4.y,wv4.z,wv4.w};
#pragma unroll
        for (int c=0;c<4;c++)
#pragma unroll
            for (int j=0;j<8;j++){
                aq[c][j] = fmaf(wqv[c], xv[j], aq[c][j]);
                ak[c][j] = fmaf(wkv[c], xv[j], ak[c][j]);
                av[c][j] = fmaf(wvv[c], xv[j], av[c][j]);
            }
    }

    // ---- q/k maxpool over the 16x16 tile (warp owns 4 channels, all 256 px) ----
    float qm[4], km[4];
#pragma unroll
    for (int c=0;c<4;c++){
        float mq=-1e30f, mk=-1e30f;
#pragma unroll
        for (int j=0;j<8;j++){ mq=fmaxf(mq,aq[c][j]); mk=fmaxf(mk,ak[c][j]); }
        qm[c]=warp_max(mq); km[c]=warp_max(mk);
    }
    if (lane < 4){
        int o = ((b*128 + g*32 + c0 + lane)*16 + tY)*16 + tX;
        g_qpool[o] = qm[lane];
        g_kpool[o] = km[lane];
    }

    // ---- v: stash to smem (reuse xs), then folded dw4x4 stride-4 ----
    __syncthreads();            // everyone done reading xs
#pragma unroll
    for (int c=0;c<4;c++){
        *(float4*)&xs[c0+c][px0]   = make_float4(av[c][0],av[c][1],av[c][2],av[c][3]);
        *(float4*)&xs[c0+c][px0+4] = make_float4(av[c][4],av[c][5],av[c][6],av[c][7]);
    }
    __syncthreads();
    {
        int c = lane;                 // channel within group
        int s = ch4;                  // 0..7
        int gc = g*32 + c;
        float vpbv = vpb[gc];
        float vw16[16];
#pragma unroll
        for (int t=0;t<16;t++) vw16[t] = vpw[gc*16 + t];
#pragma unroll
        for (int gi2=0; gi2<2; gi2++){
            int gidx = s*2 + gi2;
            int gy = gidx>>2, gx = gidx&3;
            float vsum = vpbv;
#pragma unroll
            for (int t=0;t<16;t++){
                int p = (gy*4 + (t>>2))*16 + gx*4 + (t&3);
                vsum = fmaf(vw16[t], xs[c][p], vsum);
            }
            int oh = tY*4 + gy, ow = tX*4 + gx;
            g_vpool[((size_t)(b*128+gc)*64 + oh)*64 + ow] = vsum;
        }
    }
}

// ---------------- K3: depthwise 3x3 VALID on pooled (16,16)->(14,14) ----------------
__global__ void dw3_kernel(const float* __restrict__ qpw, const float* __restrict__ qpb,
                           const float* __restrict__ kpw, const float* __restrict__ kpb){
    int bc = blockIdx.x;               // b*128+c
    int c  = bc & 127;
    __shared__ float sq[256], sk[256];
    int tid = threadIdx.x;
    sq[tid] = g_qpool[bc*256 + tid];
    sk[tid] = g_kpool[bc*256 + tid];
    __syncthreads();
    if (tid < 196){
        int y = tid/14, xx = tid - y*14;
        float aq = qpb[c], ak = kpb[c];
#pragma unroll
        for (int dy=0;dy<3;dy++)
#pragma unroll
            for (int dx=0;dx<3;dx++){
                float wq1 = qpw[c*9 + dy*3 + dx];
                float wk1 = kpw[c*9 + dy*3 + dx];
                aq = fmaf(wq1, sq[(y+dy)*16 + xx+dx], aq);
                ak = fmaf(wk1, sk[(y+dy)*16 + xx+dx], ak);
            }
        g_qf[bc*196 + tid] = aq;
        g_kf[bc*196 + tid] = ak;
    }
}

// ---------------- K4: L2 normalize rows of length 49 (in place) ----------------
__global__ void norm_kernel(){
    int idx = blockIdx.x*256 + threadIdx.x;   // < 8192
    int t = idx >> 12, r = idx & 4095;
    int b = r >> 9, rem = r & 511;
    int h = rem >> 7, cc = rem & 127;
    float* p = (t ? g_kf : g_qf) + (b*128+cc)*196 + h*49;
    float s = 0.0f;
#pragma unroll
    for (int j=0;j<49;j++) s = fmaf(p[j], p[j], s);
    float inv = 1.0f / fmaxf(sqrtf(s), 1e-12f);
#pragma unroll
    for (int j=0;j<49;j++) p[j] *= inv;
}

// ---------------- K5: sim = qn.kn * scale + bias ----------------
// grid 64 = (b*4+h)*2 + half, 256 threads
__global__ __launch_bounds__(256) void sim_kernel(const float* __restrict__ logit_scale){
    __shared__ float qn[128*49];
    __shared__ float kn[64*49];
    int blk = blockIdx.x;
    int bh = blk >> 1, half = blk & 1;
    int b = bh >> 2, h = bh & 3;
    int tid = threadIdx.x;
    for (int e=tid; e<6272; e+=256){
        int cc = e/49, j = e - cc*49;
        qn[e] = g_qf[(b*128+cc)*196 + h*49 + j];
    }
    for (int e=tid; e<3136; e+=256){
        int dd = e/49, j = e - dd*49;
        kn[e] = g_kf[(b*128 + half*64 + dd)*196 + h*49 + j];
    }
    __syncthreads();
    float scale = expf(fminf(logit_scale[h], 4.6051701860f));
    int c = tid >> 1, d0 = (tid & 1)*32;
    const float* qrow = qn + c*49;
    float acc[32];
#pragma unroll
    for (int dd=0;dd<32;dd++) acc[dd] = 0.0f;
    for (int j=0;j<49;j++){
        float qv = qrow[j];
#pragma unroll 8
        for (int dd=0;dd<32;dd++)
            acc[dd] = fmaf(qv, kn[(d0+dd)*49 + j], acc[dd]);
    }
    float* out = g_sim + ((size_t)(b*4+h)*128 + c)*128 + half*64 + d0;
    const float* bs = g_bias + h*16384 + c*128 + half*64 + d0;
#pragma unroll
    for (int dd=0;dd<32;dd++) out[dd] = fmaf(acc[dd], scale, bs[dd]);
}

// ---------------- K6: double softmax over rows of 128 (in place) ----------------
__global__ void softmax_kernel(){
    int tid = threadIdx.x;
    int warp = tid >> 5, lane = tid & 31;
    int row = blockIdx.x*8 + warp;            // < 4096
    float* p = g_sim + (size_t)row*128;
    float v[4];
#pragma unroll
    for (int j=0;j<4;j++) v[j] = p[j*32 + lane];
    float m = fmaxf(fmaxf(v[0],v[1]), fmaxf(v[2],v[3]));
    m = warp_max(m);
    float s = 0.0f;
#pragma unroll
    for (int j=0;j<4;j++){ v[j] = expf(v[j]-m); s += v[j]; }
    s = warp_sum(s);
    float inv = 1.0f/s;
#pragma unroll
    for (int j=0;j<4;j++) v[j] = 1.0f - v[j]*inv;   // y = 1 - softmax
    float m2 = fmaxf(fmaxf(v[0],v[1]), fmaxf(v[2],v[3]));
    m2 = warp_max(m2);
    float s2 = 0.0f;
#pragma unroll
    for (int j=0;j<4;j++){ v[j] = expf(v[j]-m2); s2 += v[j]; }
    s2 = warp_sum(s2);
    float inv2 = 1.0f/s2;
#pragma unroll
    for (int j=0;j<4;j++) p[j*32 + lane] = v[j]*inv2;
}

// ---------------- K7: attn out = sim @ v  ----------------
// grid (16 ptile, 4 h, 8 b), 256 threads; 64 pos per block
__global__ __launch_bounds__(256) void attn_kernel(){
    __shared__ float vs[128][64];
    int pt = blockIdx.x, h = blockIdx.y, b = blockIdx.z;
    int tid = threadIdx.x;
    for (int e=tid; e<8192; e+=256){
        int d = e>>6, p = e&63;
        vs[d][p] = g_vpool[(size_t)(b*128+d)*4096 + h*1024 + pt*64 + p];
    }
    __syncthreads();
    int c = tid >> 1, p0 = (tid & 1)*32;
    const float* simrow = g_sim + ((size_t)(b*4+h)*128 + c)*128;
    float acc[32];
#pragma unroll
    for (int i=0;i<32;i++) acc[i] = 0.0f;
    for (int d=0; d<128; d++){
        float sv = __ldg(simrow + d);
#pragma unroll
        for (int i=0;i<8;i++){
            float4 xv = *(const float4*)&vs[d][p0 + 4*i];
            acc[4*i+0] = fmaf(sv, xv.x, acc[4*i+0]);
            acc[4*i+1] = fmaf(sv, xv.y, acc[4*i+1]);
            acc[4*i+2] = fmaf(sv, xv.z, acc[4*i+2]);
            acc[4*i+3] = fmaf(sv, xv.w, acc[4*i+3]);
        }
    }
    float* out = g_attn + (size_t)(b*128+c)*4096 + h*1024 + pt*64 + p0;
#pragma unroll
    for (int i=0;i<8;i++)
        *(float4*)&out[4*i] = make_float4(acc[4*i], acc[4*i+1], acc[4*i+2], acc[4*i+3]);
}

// ---------------- K8: proj1 (128->128 1x1) + exact GELU ----------------
__global__ __launch_bounds__(256) void proj1_kernel(const float* __restrict__ w,
                                                    const float* __restrict__ bias){
    __shared__ float in_s[128][64];   // 32KB
    __shared__ float ws[32][128];     // 16KB
    int pt = blockIdx.x, b = blockIdx.y;
    int tid = threadIdx.x;
    for (int e=tid; e<8192; e+=256){
        int cc = e>>6, p = e&63;
        in_s[cc][p] = g_attn[(size_t)(b*128+cc)*4096 + pt*64 + p];
    }
    int tx = tid & 15, ty = tid >> 4;
    float acc[8][4];
#pragma unroll
    for (int j=0;j<8;j++)
#pragma unroll
        for (int jj=0;jj<4;jj++) acc[j][jj] = 0.0f;
    for (int kb=0; kb<4; kb++){
        __syncthreads();
        for (int e=tid; e<4096; e+=256){
            int cc = e>>5, kk = e&31;
            ws[kk][cc] = w[cc*128 + kb*32 + kk];
        }
        __syncthreads();
#pragma unroll 4
        for (int kk=0; kk<32; kk++){
            float4 xv = *(const float4*)&in_s[kb*32+kk][tx*4];
            float4 wa = *(const float4*)&ws[kk][ty*8];
            float4 wb = *(const float4*)&ws[kk][ty*8+4];
            float wv[8] = {wa.x,wa.y,wa.z,wa.w,wb.x,wb.y,wb.z,wb.w};
#pragma unroll
            for (int j=0;j<8;j++){
                acc[j][0] = fmaf(wv[j], xv.x, acc[j][0]);
                acc[j][1] = fmaf(wv[j], xv.y, acc[j][1]);
                acc[j][2] = fmaf(wv[j], xv.z, acc[j][2]);
                acc[j][3] = fmaf(wv[j], xv.w, acc[j][3]);
            }
        }
    }
#pragma unroll
    for (int j=0;j<8;j++){
        int cc = ty*8 + j;
        float bv = bias[cc];
        float* out = g_mid + (size_t)(b*128+cc)*4096 + pt*64 + tx*4;
#pragma unroll
        for (int jj=0;jj<4;jj++) out[jj] = gelu_exact(acc[j][jj] + bv);
    }
}

// ---------------- K9: proj2 (128->256 1x1) ----------------
__global__ __launch_bounds__(256) void proj2_kernel(const float* __restrict__ w,
                                                    const float* __restrict__ bias){
    __shared__ float in_s[128][64];
    __shared__ float ws[32][128];
    int pt = blockIdx.x, b = blockIdx.y;
    int tid = threadIdx.x;
    for (int e=tid; e<8192; e+=256){
        int cc = e>>6, p = e&63;
        in_s[cc][p] = g_mid[(size_t)(b*128+cc)*4096 + pt*64 + p];
    }
    int tx = tid & 15, ty = tid >> 4;
    for (int och=0; och<2; och++){
        float acc[8][4];
#pragma unroll
        for (int j=0;j<8;j++)
#pragma unroll
            for (int jj=0;jj<4;jj++) acc[j][jj] = 0.0f;
        for (int kb=0; kb<4; kb++){
            __syncthreads();
            for (int e=tid; e<4096; e+=256){
                int cc = e>>5, kk = e&31;
                ws[kk][cc] = w[(och*128+cc)*128 + kb*32 + kk];
            }
            __syncthreads();
#pragma unroll 4
            for (int kk=0; kk<32; kk++){
                float4 xv = *(const float4*)&in_s[kb*32+kk][tx*4];
                float4 wa = *(const float4*)&ws[kk][ty*8];
                float4 wb = *(const float4*)&ws[kk][ty*8+4];
                float wv[8] = {wa.x,wa.y,wa.z,wa.w,wb.x,wb.y,wb.z,wb.w};
#pragma unroll
                for (int j=0;j<8;j++){
                    acc[j][0] = fmaf(wv[j], xv.x, acc[j][0]);
                    acc[j][1] = fmaf(wv[j], xv.y, acc[j][1]);
                    acc[j][2] = fmaf(wv[j], xv.z, acc[j][2]);
                    acc[j][3] = fmaf(wv[j], xv.w, acc[j][3]);
                }
            }
        }
#pragma unroll
        for (int j=0;j<8;j++){
            int o = och*128 + ty*8 + j;
            float bv = bias[o];
            float* out = g_proj + (size_t)(b*256+o)*4096 + pt*64 + tx*4;
#pragma unroll
            for (int jj=0;jj<4;jj++) out[jj] = acc[j][jj] + bv;
        }
    }
}

// ---------------- K10: shortcut 4x4-s4 conv (the big GEMM) ----------------
__global__ __launch_bounds__(256) void sc_kernel(const float* __restrict__ x,
                                                 const float* __restrict__ w,
                                                 const float* __restrict__ cb){
    __shared__ float xs[4][4][64];     // [ky][kx][ow]
    __shared__ float Ws[16][68];       // [t][o], padded
    int ob = blockIdx.x, oh = blockIdx.y, b = blockIdx.z;
    int tid = threadIdx.x;
    int tx = tid & 15, ty = tid >> 4;
    float acc[4][4];
#pragma unroll
    for (int i=0;i<4;i++)
#pragma unroll
        for (int j=0;j<4;j++) acc[i][j] = 0.0f;

    int wo = tid >> 2, wt4 = (tid & 3)*4;
    for (int c=0; c<128; c++){
        __syncthreads();
        {
            const float* xrow = x + ((size_t)(b*128+c)*256 + oh*4)*256;
#pragma unroll
            for (int r=0;r<4;r++){
                float v = xrow[r*256 + tid];
                xs[r][tid&3][tid>>2] = v;
            }
            float4 wf = *(const float4*)&w[((size_t)(ob*64+wo)*128 + c)*16 + wt4];
            Ws[wt4+0][wo] = wf.x; Ws[wt4+1][wo] = wf.y;
            Ws[wt4+2][wo] = wf.z; Ws[wt4+3][wo] = wf.w;
        }
        __syncthreads();
#pragma unroll
        for (int ky=0;ky<4;ky++)
#pragma unroll
            for (int kx=0;kx<4;kx++){
                int t = ky*4 + kx;
                float4 wv = *(const float4*)&Ws[t][ty*4];
                float4 xv = *(const float4*)&xs[ky][kx][tx*4];
                acc[0][0]=fmaf(wv.x,xv.x,acc[0][0]); acc[0][1]=fmaf(wv.x,xv.y,acc[0][1]);
                acc[0][2]=fmaf(wv.x,xv.z,acc[0][2]); acc[0][3]=fmaf(wv.x,xv.w,acc[0][3]);
                acc[1][0]=fmaf(wv.y,xv.x,acc[1][0]); acc[1][1]=fmaf(wv.y,xv.y,acc[1][1]);
                acc[1][2]=fmaf(wv.y,xv.z,acc[1][2]); acc[1][3]=fmaf(wv.y,xv.w,acc[1][3]);
                acc[2][0]=fmaf(wv.z,xv.x,acc[2][0]); acc[2][1]=fmaf(wv.z,xv.y,acc[2][1]);
                acc[2][2]=fmaf(wv.z,xv.z,acc[2][2]); acc[2][3]=fmaf(wv.z,xv.w,acc[2][3]);
                acc[3][0]=fmaf(wv.w,xv.x,acc[3][0]); acc[3][1]=fmaf(wv.w,xv.y,acc[3][1]);
                acc[3][2]=fmaf(wv.w,xv.z,acc[3][2]); acc[3][3]=fmaf(wv.w,xv.w,acc[3][3]);
            }
    }
#pragma unroll
    for (int i=0;i<4;i++){
        int o = ob*64 + ty*4 + i;
        float bv = cb[o];
        float* out = g_scv + (size_t)(b*256+o)*4096 + oh*64 + tx*4;
        *(float4*)out = make_float4(acc[i][0]+bv, acc[i][1]+bv, acc[i][2]+bv, acc[i][3]+bv);
    }
}

// ---------------- K11a: per-column LN stats for proj & sc ----------------
__global__ void stats_kernel(){
    int pos = blockIdx.x*256 + threadIdx.x;
    int b = blockIdx.y;
    const float* p1 = g_proj + (size_t)b*256*4096 + pos;
    const float* p2 = g_scv  + (size_t)b*256*4096 + pos;
    float s1=0.f,q1=0.f,s2=0.f,q2=0.f;
    for (int ch=0; ch<256; ch++){
        float v1 = p1[(size_t)ch*4096];
        float v2 = p2[(size_t)ch*4096];
        s1 += v1; q1 = fmaf(v1,v1,q1);
        s2 += v2; q2 = fmaf(v2,v2,q2);
    }
    float mu1 = s1*(1.0f/256.0f), mu2 = s2*(1.0f/256.0f);
    float r1 = rsqrtf(fmaxf(q1*(1.0f/256.0f) - mu1*mu1, 0.0f) + 1e-5f);
    float r2 = rsqrtf(fmaxf(q2*(1.0f/256.0f) - mu2*mu2, 0.0f) + 1e-5f);
    float4* st = (float4*)g_stats;
    st[(size_t)b*4096 + pos] = make_float4(mu1, r1, mu2, r2);
}

// ---------------- K11b: apply both LNs, write tuple element 0 ----------------
__global__ void apply_kernel(float* __restrict__ out,
                             const float* __restrict__ g1, const float* __restrict__ be1,
                             const float* __restrict__ g2, const float* __restrict__ be2){
    size_t idx = (size_t)blockIdx.x*256 + threadIdx.x;
    int pos = (int)(idx & 4095);
    int bo  = (int)(idx >> 12);
    int o = bo & 255, b = bo >> 8;
    float4 st = ((const float4*)g_stats)[(size_t)b*4096 + pos];
    float v1 = g_proj[idx], v2 = g_scv[idx];
    out[idx] = (v1 - st.x)*st.y*g1[o] + be1[o] + (v2 - st.z)*st.w*g2[o] + be2[o];
}

// ---------------- launch ----------------
extern "C" void kernel_launch(void* const* d_in, const int* in_sizes, int n_in,
                              void* d_out, int out_size){
    const float* x    = (const float*)d_in[0];
    const float* q_w  = (const float*)d_in[1];
    const float* q_b  = (const float*)d_in[2];
    const float* k_w  = (const float*)d_in[3];
    const float* k_b  = (const float*)d_in[4];
    const float* v_w  = (const float*)d_in[5];
    const float* v_b  = (const float*)d_in[6];
    const float* qp_w = (const float*)d_in[7];
    const float* qp_b = (const float*)d_in[8];
    const float* kp_w = (const float*)d_in[9];
    const float* kp_b = (const float*)d_in[10];
    const float* vp_w = (const float*)d_in[11];
    const float* vp_b = (const float*)d_in[12];
    const float* lscale = (const float*)d_in[13];
    const float* cpb_w1 = (const float*)d_in[14];
    const float* cpb_b1 = (const float*)d_in[15];
    const float* cpb_w2 = (const float*)d_in[16];
    const float* pw1 = (const float*)d_in[17];
    const float* pb1 = (const float*)d_in[18];
    const float* pw2 = (const float*)d_in[19];
    const float* pb2 = (const float*)d_in[20];
    const float* ng  = (const float*)d_in[21];
    const float* nbe = (const float*)d_in[22];
    const float* sc_w  = (const float*)d_in[23];
    const float* sc_cb = (const float*)d_in[24];
    const float* sc_g  = (const float*)d_in[25];
    const float* sc_be = (const float*)d_in[26];
    float* out = (float*)d_out;

    cudaMemcpyAsync(out + OUT0_ELEMS, x, (size_t)X_ELEMS*sizeof(float),
                    cudaMemcpyDeviceToDevice, 0);
    bias_kernel<<<64, 256>>>(cpb_w1, cpb_b1, cpb_w2);
    qkv_kernel<<<dim3(256,32), 256>>>(x, q_w,q_b, k_w,k_b, v_w,v_b, vp_w,vp_b);
    dw3_kernel<<<1024, 256>>>(qp_w, qp_b, kp_w, kp_b);
    norm_kernel<<<32, 256>>>();
    sim_kernel<<<64, 256>>>(lscale);
    softmax_kernel<<<512, 256>>>();
    attn_kernel<<<dim3(16,4,8), 256>>>();
    proj1_kernel<<<dim3(64,8), 256>>>(pw1, pb1);
    sc_kernel<<<dim3(4,64,8), 256>>>(x, sc_w, sc_cb);
    proj2_kernel<<<dim3(64,8), 256>>>(pw2, pb2);
    stats_kernel<<<dim3(16,8), 256>>>();
    apply_kernel<<<OUT0_ELEMS/256, 256>>>(out, ng, nbe, sc_g, sc_be);
}

// round 12
// speedup vs baseline: 1.0025x; 1.0025x over previous
#include <cuda_runtime.h>
#include <math.h>
#include <stdint.h>

// B=8, C=128, H=W=256, OC=256, HEADS=4, NB=4, PS=4, OS=16
// q/k: pool16 -> (16,16) -> dw3x3 VALID -> (14,14)=196, per head 49
// v: dw4x4 s4 -> (64,64)=4096, per head 1024
// out tuple: (8,256,64,64) then x (8,128,256,256)

#define OUT0_ELEMS (8*256*64*64)      // 8388608
#define X_ELEMS    (8*128*256*256)    // 67108864

// ---------------- device scratch ----------------
__device__ float g_qpool[8*128*256];
__device__ float g_kpool[8*128*256];
__device__ float g_qf[8*128*196];
__device__ float g_kf[8*128*196];
__device__ float g_vpool[8*128*4096];
__device__ float g_bias[4*128*128];
__device__ float g_sim[8*4*128*128];
__device__ float g_attn[8*128*4096];
__device__ float g_mid[8*128*4096];
__device__ float g_proj[8*256*4096];
__device__ float g_scv[8*256*4096];
__device__ float g_stats[8*4096*4];

__device__ __forceinline__ float warp_max(float v){
#pragma unroll
    for (int o=16;o;o>>=1) v = fmaxf(v, __shfl_xor_sync(0xffffffffu,v,o));
    return v;
}
__device__ __forceinline__ float warp_sum(float v){
#pragma unroll
    for (int o=16;o;o>>=1) v += __shfl_xor_sync(0xffffffffu,v,o);
    return v;
}
__device__ __forceinline__ float gelu_exact(float x){
    return 0.5f*x*(1.0f+erff(x*0.70710678118654752440f));
}

// ---------------- K1: relative position bias ----------------
__global__ void bias_kernel(const float* __restrict__ w1, const float* __restrict__ b1,
                            const float* __restrict__ w2){
    int idx = blockIdx.x*256 + threadIdx.x;          // 0..16383
    int i = idx >> 7, j = idx & 127;
    float rel = (float)(j - i) * (8.0f/127.0f);
    float r2  = copysignf(log2f(fabsf(rel)+1.0f)*(1.0f/3.0f), rel);
    float a0=0.f,a1=0.f,a2=0.f,a3=0.f;
#pragma unroll 8
    for (int m=0;m<64;m++){
        float h = fmaxf(r2*w1[m] + b1[m], 0.0f);
        a0 += h*w2[m]; a1 += h*w2[64+m]; a2 += h*w2[128+m]; a3 += h*w2[192+m];
    }
    g_bias[0*16384+idx] = 1.0f/(1.0f+expf(-a0));
    g_bias[1*16384+idx] = 1.0f/(1.0f+expf(-a1));
    g_bias[2*16384+idx] = 1.0f/(1.0f+expf(-a2));
    g_bias[3*16384+idx] = 1.0f/(1.0f+expf(-a3));
}

// ---------------- K2: fused q/k/v grouped conv + q/k pool16 + v dw4x4-s4 ----------------
// grid (256 tiles, 32 = b*4+g), 256 threads.
// Register tiling: each thread computes 4 channels x 8 pixels for q,k,v
// (96 FMA per k-step vs 5 LDS.128 -> FMA-bound).
__global__ __launch_bounds__(256) void qkv_kernel(
    const float* __restrict__ x,
    const float* __restrict__ qw, const float* __restrict__ qb,
    const float* __restrict__ kw, const float* __restrict__ kb,
    const float* __restrict__ vw, const float* __restrict__ vb,
    const float* __restrict__ vpw, const float* __restrict__ vpb){
    __shared__ float xs[32][256];     // input tile / later reused for v
    __shared__ float wqs[32][32];     // [i][c]
    __shared__ float wks[32][32];
    __shared__ float wvs[32][32];
    int tid = threadIdx.x;
    int bg = blockIdx.y; int b = bg>>2, g = bg&3;
    int tY = blockIdx.x>>4, tX = blockIdx.x&15;

    for (int e=tid; e<1024; e+=256){
        int c = e>>5, i = e&31;
        int gi = (g*32+c)*32 + i;
        wqs[i][c] = qw[gi]; wks[i][c] = kw[gi]; wvs[i][c] = vw[gi];
    }
    {
        const float* xbp = x + (size_t)(b*128 + g*32)*65536
                             + (size_t)(tY*16 + (tid>>4))*256 + tX*16 + (tid&15);
#pragma unroll
        for (int i=0;i<32;i++) xs[i][tid] = xbp[(size_t)i*65536];
    }
    __syncthreads();

    int ch4 = tid >> 5;               // warp id -> channels [ch4*4, ch4*4+4)
    int lane = tid & 31;
    int px0 = lane * 8;               // 8 consecutive pixels (half a row)
    int c0 = ch4 * 4;

    float aq[4][8], ak[4][8], av[4][8];
#pragma unroll
    for (int c=0;c<4;c++){
        float qb0 = qb[g*32 + c0 + c], kb0 = kb[g*32 + c0 + c], vb0 = vb[g*32 + c0 + c];
#pragma unroll
        for (int j=0;j<8;j++){ aq[c][j]=qb0; ak[c][j]=kb0; av[c][j]=vb0; }
    }

#pragma unroll 8
    for (int i=0;i<32;i++){
        float4 xa = *(const float4*)&xs[i][px0];
        float4 xb2 = *(const float4*)&xs[i][px0+4];
        float xv[8] = {xa.x,xa.y,xa.z,xa.w, xb2.x,xb2.y,xb2.z,xb2.w};
        float4 wq4 = *(const float4*)&wqs[i][c0];
        float4 wk4 = *(const float4*)&wks[i][c0];
        float4 wv4 = *(const float4*)&wvs[i][c0];
        float wqv[4]={wq4.x,wq4.y,wq4.z,wq4.w};
        float wkv[4]={wk4.x,wk4.y,wk4.z,wk4.w};
        float wvv[4]={wv4.x,wv4.y,wv4.z,wv4.w};
#pragma unroll
        for (int c=0;c<4;c++)
#pragma unroll
            for (int j=0;j<8;j++){
                aq[c][j] = fmaf(wqv[c], xv[j], aq[c][j]);
                ak[c][j] = fmaf(wkv[c], xv[j], ak[c][j]);
                av[c][j] = fmaf(wvv[c], xv[j], av[c][j]);
            }
    }

    // ---- q/k maxpool over the 16x16 tile (warp owns 4 channels, all 256 px) ----
    float qm[4], km[4];
#pragma unroll
    for (int c=0;c<4;c++){
        float mq=-1e30f, mk=-1e30f;
#pragma unroll
        for (int j=0;j<8;j++){ mq=fmaxf(mq,aq[c][j]); mk=fmaxf(mk,ak[c][j]); }
        qm[c]=warp_max(mq); km[c]=warp_max(mk);
    }
    if (lane < 4){
        int o = ((b*128 + g*32 + c0 + lane)*16 + tY)*16 + tX;
        g_qpool[o] = qm[lane];
        g_kpool[o] = km[lane];
    }

    // ---- v: stash to smem (reuse xs), then folded dw4x4 stride-4 ----
    __syncthreads();            // everyone done reading xs
#pragma unroll
    for (int c=0;c<4;c++){
        *(float4*)&xs[c0+c][px0]   = make_float4(av[c][0],av[c][1],av[c][2],av[c][3]);
        *(float4*)&xs[c0+c][px0+4] = make_float4(av[c][4],av[c][5],av[c][6],av[c][7]);
    }
    __syncthreads();
    {
        int c = lane;                 // channel within group
        int s = ch4;                  // 0..7
        int gc = g*32 + c;
        float vpbv = vpb[gc];
        float vw16[16];
#pragma unroll
        for (int t=0;t<16;t++) vw16[t] = vpw[gc*16 + t];
#pragma unroll
        for (int gi2=0; gi2<2; gi2++){
            int gidx = s*2 + gi2;
            int gy = gidx>>2, gx = gidx&3;
            float vsum = vpbv;
#pragma unroll
            for (int t=0;t<16;t++){
                int p = (gy*4 + (t>>2))*16 + gx*4 + (t&3);
                vsum = fmaf(vw16[t], xs[c][p], vsum);
            }
            int oh = tY*4 + gy, ow = tX*4 + gx;
            g_vpool[((size_t)(b*128+gc)*64 + oh)*64 + ow] = vsum;
        }
    }
}

// ---------------- K3: depthwise 3x3 VALID on pooled (16,16)->(14,14) ----------------
__global__ void dw3_kernel(const float* __restrict__ qpw, const float* __restrict__ qpb,
                           const float* __restrict__ kpw, const float* __restrict__ kpb){
    int bc = blockIdx.x;               // b*128+c
    int c  = bc & 127;
    __shared__ float sq[256], sk[256];
    int tid = threadIdx.x;
    sq[tid] = g_qpool[bc*256 + tid];
    sk[tid] = g_kpool[bc*256 + tid];
    __syncthreads();
    if (tid < 196){
        int y = tid/14, xx = tid - y*14;
        float aq = qpb[c], ak = kpb[c];
#pragma unroll
        for (int dy=0;dy<3;dy++)
#pragma unroll
            for (int dx=0;dx<3;dx++){
                float wq1 = qpw[c*9 + dy*3 + dx];
                float wk1 = kpw[c*9 + dy*3 + dx];
                aq = fmaf(wq1, sq[(y+dy)*16 + xx+dx], aq);
                ak = fmaf(wk1, sk[(y+dy)*16 + xx+dx], ak);
            }
        g_qf[bc*196 + tid] = aq;
        g_kf[bc*196 + tid] = ak;
    }
}

// ---------------- K4: L2 normalize rows of length 49 (in place) ----------------
__global__ void norm_kernel(){
    int idx = blockIdx.x*256 + threadIdx.x;   // < 8192
    int t = idx >> 12, r = idx & 4095;
    int b = r >> 9, rem = r & 511;
    int h = rem >> 7, cc = rem & 127;
    float* p = (t ? g_kf : g_qf) + (b*128+cc)*196 + h*49;
    float s = 0.0f;
#pragma unroll
    for (int j=0;j<49;j++) s = fmaf(p[j], p[j], s);
    float inv = 1.0f / fmaxf(sqrtf(s), 1e-12f);
#pragma unroll
    for (int j=0;j<49;j++) p[j] *= inv;
}

// ---------------- K5: sim = qn.kn * scale + bias ----------------
// grid 64 = (b*4+h)*2 + half, 256 threads
__global__ __launch_bounds__(256) void sim_kernel(const float* __restrict__ logit_scale){
    __shared__ float qn[128*49];
    __shared__ float kn[64*49];
    int blk = blockIdx.x;
    int bh = blk >> 1, half = blk & 1;
    int b = bh >> 2, h = bh & 3;
    int tid = threadIdx.x;
    for (int e=tid; e<6272; e+=256){
        int cc = e/49, j = e - cc*49;
        qn[e] = g_qf[(b*128+cc)*196 + h*49 + j];
    }
    for (int e=tid; e<3136; e+=256){
        int dd = e/49, j = e - dd*49;
        kn[e] = g_kf[(b*128 + half*64 + dd)*196 + h*49 + j];
    }
    __syncthreads();
    float scale = expf(fminf(logit_scale[h], 4.6051701860f));
    int c = tid >> 1, d0 = (tid & 1)*32;
    const float* qrow = qn + c*49;
    float acc[32];
#pragma unroll
    for (int dd=0;dd<32;dd++) acc[dd] = 0.0f;
    for (int j=0;j<49;j++){
        float qv = qrow[j];
#pragma unroll 8
        for (int dd=0;dd<32;dd++)
            acc[dd] = fmaf(qv, kn[(d0+dd)*49 + j], acc[dd]);
    }
    float* out = g_sim + ((size_t)(b*4+h)*128 + c)*128 + half*64 + d0;
    const float* bs = g_bias + h*16384 + c*128 + half*64 + d0;
#pragma unroll
    for (int dd=0;dd<32;dd++) out[dd] = fmaf(acc[dd], scale, bs[dd]);
}

// ---------------- K6: double softmax over rows of 128 (in place) ----------------
__global__ void softmax_kernel(){
    int tid = threadIdx.x;
    int warp = tid >> 5, lane = tid & 31;
    int row = blockIdx.x*8 + warp;            // < 4096
    float* p = g_sim + (size_t)row*128;
    float v[4];
#pragma unroll
    for (int j=0;j<4;j++) v[j] = p[j*32 + lane];
    float m = fmaxf(fmaxf(v[0],v[1]), fmaxf(v[2],v[3]));
    m = warp_max(m);
    float s = 0.0f;
#pragma unroll
    for (int j=0;j<4;j++){ v[j] = expf(v[j]-m); s += v[j]; }
    s = warp_sum(s);
    float inv = 1.0f/s;
#pragma unroll
    for (int j=0;j<4;j++) v[j] = 1.0f - v[j]*inv;   // y = 1 - softmax
    float m2 = fmaxf(fmaxf(v[0],v[1]), fmaxf(v[2],v[3]));
    m2 = warp_max(m2);
    float s2 = 0.0f;
#pragma unroll
    for (int j=0;j<4;j++){ v[j] = expf(v[j]-m2); s2 += v[j]; }
    s2 = warp_sum(s2);
    float inv2 = 1.0f/s2;
#pragma unroll
    for (int j=0;j<4;j++) p[j*32 + lane] = v[j]*inv2;
}

// ---------------- K7: attn out = sim @ v  ----------------
// grid (16 ptile, 4 h, 8 b), 256 threads; 64 pos per block
__global__ __launch_bounds__(256) void attn_kernel(){
    __shared__ float vs[128][64];
    int pt = blockIdx.x, h = blockIdx.y, b = blockIdx.z;
    int tid = threadIdx.x;
    for (int e=tid; e<8192; e+=256){
        int d = e>>6, p = e&63;
        vs[d][p] = g_vpool[(size_t)(b*128+d)*4096 + h*1024 + pt*64 + p];
    }
    __syncthreads();
    int c = tid >> 1, p0 = (tid & 1)*32;
    const float* simrow = g_sim + ((size_t)(b*4+h)*128 + c)*128;
    float acc[32];
#pragma unroll
    for (int i=0;i<32;i++) acc[i] = 0.0f;
    for (int d=0; d<128; d++){
        float sv = __ldg(simrow + d);
#pragma unroll
        for (int i=0;i<8;i++){
            float4 xv = *(const float4*)&vs[d][p0 + 4*i];
            acc[4*i+0] = fmaf(sv, xv.x, acc[4*i+0]);
            acc[4*i+1] = fmaf(sv, xv.y, acc[4*i+1]);
            acc[4*i+2] = fmaf(sv, xv.z, acc[4*i+2]);
            acc[4*i+3] = fmaf(sv, xv.w, acc[4*i+3]);
        }
    }
    float* out = g_attn + (size_t)(b*128+c)*4096 + h*1024 + pt*64 + p0;
#pragma unroll
    for (int i=0;i<8;i++)
        *(float4*)&out[4*i] = make_float4(acc[4*i], acc[4*i+1], acc[4*i+2], acc[4*i+3]);
}

// ---------------- K8: proj1 (128->128 1x1) + exact GELU ----------------
__global__ __launch_bounds__(256) void proj1_kernel(const float* __restrict__ w,
                                                    const float* __restrict__ bias){
    __shared__ float in_s[128][64];   // 32KB
    __shared__ float ws[32][128];     // 16KB
    int pt = blockIdx.x, b = blockIdx.y;
    int tid = threadIdx.x;
    for (int e=tid; e<8192; e+=256){
        int cc = e>>6, p = e&63;
        in_s[cc][p] = g_attn[(size_t)(b*128+cc)*4096 + pt*64 + p];
    }
    int tx = tid & 15, ty = tid >> 4;
    float acc[8][4];
#pragma unroll
    for (int j=0;j<8;j++)
#pragma unroll
        for (int jj=0;jj<4;jj++) acc[j][jj] = 0.0f;
    for (int kb=0; kb<4; kb++){
        __syncthreads();
        for (int e=tid; e<4096; e+=256){
            int cc = e>>5, kk = e&31;
            ws[kk][cc] = w[cc*128 + kb*32 + kk];
        }
        __syncthreads();
#pragma unroll 4
        for (int kk=0; kk<32; kk++){
            float4 xv = *(const float4*)&in_s[kb*32+kk][tx*4];
            float4 wa = *(const float4*)&ws[kk][ty*8];
            float4 wb = *(const float4*)&ws[kk][ty*8+4];
            float wv[8] = {wa.x,wa.y,wa.z,wa.w,wb.x,wb.y,wb.z,wb.w};
#pragma unroll
            for (int j=0;j<8;j++){
                acc[j][0] = fmaf(wv[j], xv.x, acc[j][0]);
                acc[j][1] = fmaf(wv[j], xv.y, acc[j][1]);
                acc[j][2] = fmaf(wv[j], xv.z, acc[j][2]);
                acc[j][3] = fmaf(wv[j], xv.w, acc[j][3]);
            }
        }
    }
#pragma unroll
    for (int j=0;j<8;j++){
        int cc = ty*8 + j;
        float bv = bias[cc];
        float* out = g_mid + (size_t)(b*128+cc)*4096 + pt*64 + tx*4;
#pragma unroll
        for (int jj=0;jj<4;jj++) out[jj] = gelu_exact(acc[j][jj] + bv);
    }
}

// ---------------- K9: proj2 (128->256 1x1) ----------------
__global__ __launch_bounds__(256) void proj2_kernel(const float* __restrict__ w,
                                                    const float* __restrict__ bias){
    __shared__ float in_s[128][64];
    __shared__ float ws[32][128];
    int pt = blockIdx.x, b = blockIdx.y;
    int tid = threadIdx.x;
    for (int e=tid; e<8192; e+=256){
        int cc = e>>6, p = e&63;
        in_s[cc][p] = g_mid[(size_t)(b*128+cc)*4096 + pt*64 + p];
    }
    int tx = tid & 15, ty = tid >> 4;
    for (int och=0; och<2; och++){
        float acc[8][4];
#pragma unroll
        for (int j=0;j<8;j++)
#pragma unroll
            for (int jj=0;jj<4;jj++) acc[j][jj] = 0.0f;
        for (int kb=0; kb<4; kb++){
            __syncthreads();
            for (int e=tid; e<4096; e+=256){
                int cc = e>>5, kk = e&31;
                ws[kk][cc] = w[(och*128+cc)*128 + kb*32 + kk];
            }
            __syncthreads();
#pragma unroll 4
            for (int kk=0; kk<32; kk++){
                float4 xv = *(const float4*)&in_s[kb*32+kk][tx*4];
                float4 wa = *(const float4*)&ws[kk][ty*8];
                float4 wb = *(const float4*)&ws[kk][ty*8+4];
                float wv[8] = {wa.x,wa.y,wa.z,wa.w,wb.x,wb.y,wb.z,wb.w};
#pragma unroll
                for (int j=0;j<8;j++){
                    acc[j][0] = fmaf(wv[j], xv.x, acc[j][0]);
                    acc[j][1] = fmaf(wv[j], xv.y, acc[j][1]);
                    acc[j][2] = fmaf(wv[j], xv.z, acc[j][2]);
                    acc[j][3] = fmaf(wv[j], xv.w, acc[j][3]);
                }
            }
        }
#pragma unroll
        for (int j=0;j<8;j++){
            int o = och*128 + ty*8 + j;
            float bv = bias[o];
            float* out = g_proj + (size_t)(b*256+o)*4096 + pt*64 + tx*4;
#pragma unroll
            for (int jj=0;jj<4;jj++) out[jj] = acc[j][jj] + bv;
        }
    }
}

// ---------------- K10: shortcut 4x4-s4 conv (the big GEMM) ----------------
__global__ __launch_bounds__(256) void sc_kernel(const float* __restrict__ x,
                                                 const float* __restrict__ w,
                                                 const float* __restrict__ cb){
    __shared__ float xs[4][4][64];     // [ky][kx][ow]
    __shared__ float Ws[16][68];       // [t][o], padded
    int ob = blockIdx.x, oh = blockIdx.y, b = blockIdx.z;
    int tid = threadIdx.x;
    int tx = tid & 15, ty = tid >> 4;
    float acc[4][4];
#pragma unroll
    for (int i=0;i<4;i++)
#pragma unroll
        for (int j=0;j<4;j++) acc[i][j] = 0.0f;

    int wo = tid >> 2, wt4 = (tid & 3)*4;
    for (int c=0; c<128; c++){
        __syncthreads();
        {
            const float* xrow = x + ((size_t)(b*128+c)*256 + oh*4)*256;
#pragma unroll
            for (int r=0;r<4;r++){
                float v = xrow[r*256 + tid];
                xs[r][tid&3][tid>>2] = v;
            }
            float4 wf = *(const float4*)&w[((size_t)(ob*64+wo)*128 + c)*16 + wt4];
            Ws[wt4+0][wo] = wf.x; Ws[wt4+1][wo] = wf.y;
            Ws[wt4+2][wo] = wf.z; Ws[wt4+3][wo] = wf.w;
        }
        __syncthreads();
#pragma unroll
        for (int ky=0;ky<4;ky++)
#pragma unroll
            for (int kx=0;kx<4;kx++){
                int t = ky*4 + kx;
                float4 wv = *(const float4*)&Ws[t][ty*4];
                float4 xv = *(const float4*)&xs[ky][kx][tx*4];
                acc[0][0]=fmaf(wv.x,xv.x,acc[0][0]); acc[0][1]=fmaf(wv.x,xv.y,acc[0][1]);
                acc[0][2]=fmaf(wv.x,xv.z,acc[0][2]); acc[0][3]=fmaf(wv.x,xv.w,acc[0][3]);
                acc[1][0]=fmaf(wv.y,xv.x,acc[1][0]); acc[1][1]=fmaf(wv.y,xv.y,acc[1][1]);
                acc[1][2]=fmaf(wv.y,xv.z,acc[1][2]); acc[1][3]=fmaf(wv.y,xv.w,acc[1][3]);
                acc[2][0]=fmaf(wv.z,xv.x,acc[2][0]); acc[2][1]=fmaf(wv.z,xv.y,acc[2][1]);
                acc[2][2]=fmaf(wv.z,xv.z,acc[2][2]); acc[2][3]=fmaf(wv.z,xv.w,acc[2][3]);
                acc[3][0]=fmaf(wv.w,xv.x,acc[3][0]); acc[3][1]=fmaf(wv.w,xv.y,acc[3][1]);
                acc[3][2]=fmaf(wv.w,xv.z,acc[3][2]); acc[3][3]=fmaf(wv.w,xv.w,acc[3][3]);
            }
    }
#pragma unroll
    for (int i=0;i<4;i++){
        int o = ob*64 + ty*4 + i;
        float bv = cb[o];
        float* out = g_scv + (size_t)(b*256+o)*4096 + oh*64 + tx*4;
        *(float4*)out = make_float4(acc[i][0]+bv, acc[i][1]+bv, acc[i][2]+bv, acc[i][3]+bv);
    }
}

// ---------------- K11a: per-column LN stats for proj & sc ----------------
__global__ void stats_kernel(){
    int pos = blockIdx.x*256 + threadIdx.x;
    int b = blockIdx.y;
    const float* p1 = g_proj + (size_t)b*256*4096 + pos;
    const float* p2 = g_scv  + (size_t)b*256*4096 + pos;
    float s1=0.f,q1=0.f,s2=0.f,q2=0.f;
    for (int ch=0; ch<256; ch++){
        float v1 = p1[(size_t)ch*4096];
        float v2 = p2[(size_t)ch*4096];
        s1 += v1; q1 = fmaf(v1,v1,q1);
        s2 += v2; q2 = fmaf(v2,v2,q2);
    }
    float mu1 = s1*(1.0f/256.0f), mu2 = s2*(1.0f/256.0f);
    float r1 = rsqrtf(fmaxf(q1*(1.0f/256.0f) - mu1*mu1, 0.0f) + 1e-5f);
    float r2 = rsqrtf(fmaxf(q2*(1.0f/256.0f) - mu2*mu2, 0.0f) + 1e-5f);
    float4* st = (float4*)g_stats;
    st[(size_t)b*4096 + pos] = make_float4(mu1, r1, mu2, r2);
}

// ---------------- K11b: apply both LNs, write tuple element 0 ----------------
__global__ void apply_kernel(float* __restrict__ out,
                             const float* __restrict__ g1, const float* __restrict__ be1,
                             const float* __restrict__ g2, const float* __restrict__ be2){
    size_t idx = (size_t)blockIdx.x*256 + threadIdx.x;
    int pos = (int)(idx & 4095);
    int bo  = (int)(idx >> 12);
    int o = bo & 255, b = bo >> 8;
    float4 st = ((const float4*)g_stats)[(size_t)b*4096 + pos];
    float v1 = g_proj[idx], v2 = g_scv[idx];
    out[idx] = (v1 - st.x)*st.y*g1[o] + be1[o] + (v2 - st.z)*st.w*g2[o] + be2[o];
}

// ---------------- launch ----------------
extern "C" void kernel_launch(void* const* d_in, const int* in_sizes, int n_in,
                              void* d_out, int out_size){
    const float* x    = (const float*)d_in[0];
    const float* q_w  = (const float*)d_in[1];
    const float* q_b  = (const float*)d_in[2];
    const float* k_w  = (const float*)d_in[3];
    const float* k_b  = (const float*)d_in[4];
    const float* v_w  = (const float*)d_in[5];
    const float* v_b  = (const float*)d_in[6];
    const float* qp_w = (const float*)d_in[7];
    const float* qp_b = (const float*)d_in[8];
    const float* kp_w = (const float*)d_in[9];
    const float* kp_b = (const float*)d_in[10];
    const float* vp_w = (const float*)d_in[11];
    const float* vp_b = (const float*)d_in[12];
    const float* lscale = (const float*)d_in[13];
    const float* cpb_w1 = (const float*)d_in[14];
    const float* cpb_b1 = (const float*)d_in[15];
    const float* cpb_w2 = (const float*)d_in[16];
    const float* pw1 = (const float*)d_in[17];
    const float* pb1 = (const float*)d_in[18];
    const float* pw2 = (const float*)d_in[19];
    const float* pb2 = (const float*)d_in[20];
    const float* ng  = (const float*)d_in[21];
    const float* nbe = (const float*)d_in[22];
    const float* sc_w  = (const float*)d_in[23];
    const float* sc_cb = (const float*)d_in[24];
    const float* sc_g  = (const float*)d_in[25];
    const float* sc_be = (const float*)d_in[26];
    float* out = (float*)d_out;

    cudaMemcpyAsync(out + OUT0_ELEMS, x, (size_t)X_ELEMS*sizeof(float),
                    cudaMemcpyDeviceToDevice, 0);
    bias_kernel<<<64, 256>>>(cpb_w1, cpb_b1, cpb_w2);
    qkv_kernel<<<dim3(256,32), 256>>>(x, q_w,q_b, k_w,k_b, v_w,v_b, vp_w,vp_b);
    dw3_kernel<<<1024, 256>>>(qp_w, qp_b, kp_w, kp_b);
    norm_kernel<<<32, 256>>>();
    sim_kernel<<<64, 256>>>(lscale);
    softmax_kernel<<<512, 256>>>();
    attn_kernel<<<dim3(16,4,8), 256>>>();
    proj1_kernel<<<dim3(64,8), 256>>>(pw1, pb1);
    sc_kernel<<<dim3(4,64,8), 256>>>(x, sc_w, sc_cb);
    proj2_kernel<<<dim3(64,8), 256>>>(pw2, pb2);
    stats_kernel<<<dim3(16,8), 256>>>();
    apply_kernel<<<OUT0_ELEMS/256, 256>>>(out, ng, nbe, sc_g, sc_be);
}

// round 13
// speedup vs baseline: 1.0030x; 1.0006x over previous
#include <cuda_runtime.h>
#include <math.h>
#include <stdint.h>

// B=8, C=128, H=W=256, OC=256, HEADS=4, NB=4, PS=4, OS=16
// q/k: pool16 -> (16,16) -> dw3x3 VALID -> (14,14)=196, per head 49
// v: dw4x4 s4 -> (64,64)=4096, per head 1024
// out tuple: (8,256,64,64) then x (8,128,256,256)

#define OUT0_ELEMS (8*256*64*64)      // 8388608
#define X_ELEMS    (8*128*256*256)    // 67108864

// ---------------- device scratch ----------------
__device__ float g_qpool[8*128*256];
__device__ float g_kpool[8*128*256];
__device__ float g_qf[8*128*196];
__device__ float g_kf[8*128*196];
__device__ float g_vpool[8*128*4096];
__device__ float g_bias[4*128*128];
__device__ float g_sim[8*4*128*128];
__device__ float g_attn[8*128*4096];
__device__ float g_mid[8*128*4096];
__device__ float g_proj[8*256*4096];
__device__ float g_scv[8*256*4096];
__device__ float g_stats[8*4096*4];

__device__ __forceinline__ float warp_max(float v){
#pragma unroll
    for (int o=16;o;o>>=1) v = fmaxf(v, __shfl_xor_sync(0xffffffffu,v,o));
    return v;
}
__device__ __forceinline__ float warp_sum(float v){
#pragma unroll
    for (int o=16;o;o>>=1) v += __shfl_xor_sync(0xffffffffu,v,o);
    return v;
}
__device__ __forceinline__ float gelu_exact(float x){
    return 0.5f*x*(1.0f+erff(x*0.70710678118654752440f));
}

// ---------------- K1: relative position bias ----------------
__global__ void bias_kernel(const float* __restrict__ w1, const float* __restrict__ b1,
                            const float* __restrict__ w2){
    int idx = blockIdx.x*256 + threadIdx.x;          // 0..16383
    int i = idx >> 7, j = idx & 127;
    float rel = (float)(j - i) * (8.0f/127.0f);
    float r2  = copysignf(log2f(fabsf(rel)+1.0f)*(1.0f/3.0f), rel);
    float a0=0.f,a1=0.f,a2=0.f,a3=0.f;
#pragma unroll 8
    for (int m=0;m<64;m++){
        float h = fmaxf(r2*w1[m] + b1[m], 0.0f);
        a0 += h*w2[m]; a1 += h*w2[64+m]; a2 += h*w2[128+m]; a3 += h*w2[192+m];
    }
    g_bias[0*16384+idx] = 1.0f/(1.0f+expf(-a0));
    g_bias[1*16384+idx] = 1.0f/(1.0f+expf(-a1));
    g_bias[2*16384+idx] = 1.0f/(1.0f+expf(-a2));
    g_bias[3*16384+idx] = 1.0f/(1.0f+expf(-a3));
}

// ---------------- K2: fused q/k/v grouped conv + q/k pool16 + v dw4x4-s4 ----------------
// grid (256 tiles, 32 = b*4+g), 256 threads.
// Register tiling: each thread computes 4 channels x 8 pixels for q,k,v
// (96 FMA per k-step vs 5 LDS.128 -> FMA-bound).
__global__ __launch_bounds__(256) void qkv_kernel(
    const float* __restrict__ x,
    const float* __restrict__ qw, const float* __restrict__ qb,
    const float* __restrict__ kw, const float* __restrict__ kb,
    const float* __restrict__ vw, const float* __restrict__ vb,
    const float* __restrict__ vpw, const float* __restrict__ vpb){
    __shared__ float xs[32][256];     // input tile / later reused for v
    __shared__ float wqs[32][32];     // [i][c]
    __shared__ float wks[32][32];
    __shared__ float wvs[32][32];
    int tid = threadIdx.x;
    int bg = blockIdx.y; int b = bg>>2, g = bg&3;
    int tY = blockIdx.x>>4, tX = blockIdx.x&15;

    for (int e=tid; e<1024; e+=256){
        int c = e>>5, i = e&31;
        int gi = (g*32+c)*32 + i;
        wqs[i][c] = qw[gi]; wks[i][c] = kw[gi]; wvs[i][c] = vw[gi];
    }
    {
        const float* xbp = x + (size_t)(b*128 + g*32)*65536
                             + (size_t)(tY*16 + (tid>>4))*256 + tX*16 + (tid&15);
#pragma unroll
        for (int i=0;i<32;i++) xs[i][tid] = xbp[(size_t)i*65536];
    }
    __syncthreads();

    int ch4 = tid >> 5;               // warp id -> channels [ch4*4, ch4*4+4)
    int lane = tid & 31;
    int px0 = lane * 8;               // 8 consecutive pixels (half a row)
    int c0 = ch4 * 4;

    float aq[4][8], ak[4][8], av[4][8];
#pragma unroll
    for (int c=0;c<4;c++){
        float qb0 = qb[g*32 + c0 + c], kb0 = kb[g*32 + c0 + c], vb0 = vb[g*32 + c0 + c];
#pragma unroll
        for (int j=0;j<8;j++){ aq[c][j]=qb0; ak[c][j]=kb0; av[c][j]=vb0; }
    }

#pragma unroll 8
    for (int i=0;i<32;i++){
        float4 xa = *(const float4*)&xs[i][px0];
        float4 xb2 = *(const float4*)&xs[i][px0+4];
        float xv[8] = {xa.x,xa.y,xa.z,xa.w, xb2.x,xb2.y,xb2.z,xb2.w};
        float4 wq4 = *(const float4*)&wqs[i][c0];
        float4 wk4 = *(const float4*)&wks[i][c0];
        float4 wv4 = *(const float4*)&wvs[i][c0];
        float wqv[4]={wq4.x,wq4.y,wq4.z,wq4.w};
        float wkv[4]={wk4.x,wk4.y,wk4.z,wk4.w};
        float wvv[4]={wv4.x,wv4.y,wv4.z,wv4.w};
#pragma unroll
        for (int c=0;c<4;c++)
#pragma unroll
            for (int j=0;j<8;j++){
                aq[c][j] = fmaf(wqv[c], xv[j], aq[c][j]);
                ak[c][j] = fmaf(wkv[c], xv[j], ak[c][j]);
                av[c][j] = fmaf(wvv[c], xv[j], av[c][j]);
            }
    }

    // ---- q/k maxpool over the 16x16 tile (warp owns 4 channels, all 256 px) ----
    float qm[4], km[4];
#pragma unroll
    for (int c=0;c<4;c++){
        float mq=-1e30f, mk=-1e30f;
#pragma unroll
        for (int j=0;j<8;j++){ mq=fmaxf(mq,aq[c][j]); mk=fmaxf(mk,ak[c][j]); }
        qm[c]=warp_max(mq); km[c]=warp_max(mk);
    }
    if (lane < 4){
        int o = ((b*128 + g*32 + c0 + lane)*16 + tY)*16 + tX;
        g_qpool[o] = qm[lane];
        g_kpool[o] = km[lane];
    }

    // ---- v: stash to smem (reuse xs), then folded dw4x4 stride-4 ----
    __syncthreads();            // everyone done reading xs
#pragma unroll
    for (int c=0;c<4;c++){
        *(float4*)&xs[c0+c][px0]   = make_float4(av[c][0],av[c][1],av[c][2],av[c][3]);
        *(float4*)&xs[c0+c][px0+4] = make_float4(av[c][4],av[c][5],av[c][6],av[c][7]);
    }
    __syncthreads();
    {
        int c = lane;                 // channel within group
        int s = ch4;                  // 0..7
        int gc = g*32 + c;
        float vpbv = vpb[gc];
        float vw16[16];
#pragma unroll
        for (int t=0;t<16;t++) vw16[t] = vpw[gc*16 + t];
#pragma unroll
        for (int gi2=0; gi2<2; gi2++){
            int gidx = s*2 + gi2;
            int gy = gidx>>2, gx = gidx&3;
            float vsum = vpbv;
#pragma unroll
            for (int t=0;t<16;t++){
                int p = (gy*4 + (t>>2))*16 + gx*4 + (t&3);
                vsum = fmaf(vw16[t], xs[c][p], vsum);
            }
            int oh = tY*4 + gy, ow = tX*4 + gx;
            g_vpool[((size_t)(b*128+gc)*64 + oh)*64 + ow] = vsum;
        }
    }
}

// ---------------- K3: depthwise 3x3 VALID on pooled (16,16)->(14,14) ----------------
__global__ void dw3_kernel(const float* __restrict__ qpw, const float* __restrict__ qpb,
                           const float* __restrict__ kpw, const float* __restrict__ kpb){
    int bc = blockIdx.x;               // b*128+c
    int c  = bc & 127;
    __shared__ float sq[256], sk[256];
    int tid = threadIdx.x;
    sq[tid] = g_qpool[bc*256 + tid];
    sk[tid] = g_kpool[bc*256 + tid];
    __syncthreads();
    if (tid < 196){
        int y = tid/14, xx = tid - y*14;
        float aq = qpb[c], ak = kpb[c];
#pragma unroll
        for (int dy=0;dy<3;dy++)
#pragma unroll
            for (int dx=0;dx<3;dx++){
                float wq1 = qpw[c*9 + dy*3 + dx];
                float wk1 = kpw[c*9 + dy*3 + dx];
                aq = fmaf(wq1, sq[(y+dy)*16 + xx+dx], aq);
                ak = fmaf(wk1, sk[(y+dy)*16 + xx+dx], ak);
            }
        g_qf[bc*196 + tid] = aq;
        g_kf[bc*196 + tid] = ak;
    }
}

// ---------------- K4: L2 normalize rows of length 49 (in place) ----------------
__global__ void norm_kernel(){
    int idx = blockIdx.x*256 + threadIdx.x;   // < 8192
    int t = idx >> 12, r = idx & 4095;
    int b = r >> 9, rem = r & 511;
    int h = rem >> 7, cc = rem & 127;
    float* p = (t ? g_kf : g_qf) + (b*128+cc)*196 + h*49;
    float s = 0.0f;
#pragma unroll
    for (int j=0;j<49;j++) s = fmaf(p[j], p[j], s);
    float inv = 1.0f / fmaxf(sqrtf(s), 1e-12f);
#pragma unroll
    for (int j=0;j<49;j++) p[j] *= inv;
}

// ---------------- K5: sim = qn.kn * scale + bias ----------------
// grid 64 = (b*4+h)*2 + half, 256 threads
__global__ __launch_bounds__(256) void sim_kernel(const float* __restrict__ logit_scale){
    __shared__ float qn[128*49];
    __shared__ float kn[64*49];
    int blk = blockIdx.x;
    int bh = blk >> 1, half = blk & 1;
    int b = bh >> 2, h = bh & 3;
    int tid = threadIdx.x;
    for (int e=tid; e<6272; e+=256){
        int cc = e/49, j = e - cc*49;
        qn[e] = g_qf[(b*128+cc)*196 + h*49 + j];
    }
    for (int e=tid; e<3136; e+=256){
        int dd = e/49, j = e - dd*49;
        kn[e] = g_kf[(b*128 + half*64 + dd)*196 + h*49 + j];
    }
    __syncthreads();
    float scale = expf(fminf(logit_scale[h], 4.6051701860f));
    int c = tid >> 1, d0 = (tid & 1)*32;
    const float* qrow = qn + c*49;
    float acc[32];
#pragma unroll
    for (int dd=0;dd<32;dd++) acc[dd] = 0.0f;
    for (int j=0;j<49;j++){
        float qv = qrow[j];
#pragma unroll 8
        for (int dd=0;dd<32;dd++)
            acc[dd] = fmaf(qv, kn[(d0+dd)*49 + j], acc[dd]);
    }
    float* out = g_sim + ((size_t)(b*4+h)*128 + c)*128 + half*64 + d0;
    const float* bs = g_bias + h*16384 + c*128 + half*64 + d0;
#pragma unroll
    for (int dd=0;dd<32;dd++) out[dd] = fmaf(acc[dd], scale, bs[dd]);
}

// ---------------- K6: double softmax over rows of 128 (in place) ----------------
__global__ void softmax_kernel(){
    int tid = threadIdx.x;
    int warp = tid >> 5, lane = tid & 31;
    int row = blockIdx.x*8 + warp;            // < 4096
    float* p = g_sim + (size_t)row*128;
    float v[4];
#pragma unroll
    for (int j=0;j<4;j++) v[j] = p[j*32 + lane];
    float m = fmaxf(fmaxf(v[0],v[1]), fmaxf(v[2],v[3]));
    m = warp_max(m);
    float s = 0.0f;
#pragma unroll
    for (int j=0;j<4;j++){ v[j] = expf(v[j]-m); s += v[j]; }
    s = warp_sum(s);
    float inv = 1.0f/s;
#pragma unroll
    for (int j=0;j<4;j++) v[j] = 1.0f - v[j]*inv;   // y = 1 - softmax
    float m2 = fmaxf(fmaxf(v[0],v[1]), fmaxf(v[2],v[3]));
    m2 = warp_max(m2);
    float s2 = 0.0f;
#pragma unroll
    for (int j=0;j<4;j++){ v[j] = expf(v[j]-m2); s2 += v[j]; }
    s2 = warp_sum(s2);
    float inv2 = 1.0f/s2;
#pragma unroll
    for (int j=0;j<4;j++) p[j*32 + lane] = v[j]*inv2;
}

// ---------------- K7: attn out = sim @ v  ----------------
// grid (16 ptile, 4 h, 8 b), 256 threads; 64 pos per block
__global__ __launch_bounds__(256) void attn_kernel(){
    __shared__ float vs[128][64];
    int pt = blockIdx.x, h = blockIdx.y, b = blockIdx.z;
    int tid = threadIdx.x;
    for (int e=tid; e<8192; e+=256){
        int d = e>>6, p = e&63;
        vs[d][p] = g_vpool[(size_t)(b*128+d)*4096 + h*1024 + pt*64 + p];
    }
    __syncthreads();
    int c = tid >> 1, p0 = (tid & 1)*32;
    const float* simrow = g_sim + ((size_t)(b*4+h)*128 + c)*128;
    float acc[32];
#pragma unroll
    for (int i=0;i<32;i++) acc[i] = 0.0f;
    for (int d=0; d<128; d++){
        float sv = __ldg(simrow + d);
#pragma unroll
        for (int i=0;i<8;i++){
            float4 xv = *(const float4*)&vs[d][p0 + 4*i];
            acc[4*i+0] = fmaf(sv, xv.x, acc[4*i+0]);
            acc[4*i+1] = fmaf(sv, xv.y, acc[4*i+1]);
            acc[4*i+2] = fmaf(sv, xv.z, acc[4*i+2]);
            acc[4*i+3] = fmaf(sv, xv.w, acc[4*i+3]);
        }
    }
    float* out = g_attn + (size_t)(b*128+c)*4096 + h*1024 + pt*64 + p0;
#pragma unroll
    for (int i=0;i<8;i++)
        *(float4*)&out[4*i] = make_float4(acc[4*i], acc[4*i+1], acc[4*i+2], acc[4*i+3]);
}

// ---------------- K8: proj1 (128->128 1x1) + exact GELU ----------------
__global__ __launch_bounds__(256) void proj1_kernel(const float* __restrict__ w,
                                                    const float* __restrict__ bias){
    __shared__ float in_s[128][64];   // 32KB
    __shared__ float ws[32][128];     // 16KB
    int pt = blockIdx.x, b = blockIdx.y;
    int tid = threadIdx.x;
    for (int e=tid; e<8192; e+=256){
        int cc = e>>6, p = e&63;
        in_s[cc][p] = g_attn[(size_t)(b*128+cc)*4096 + pt*64 + p];
    }
    int tx = tid & 15, ty = tid >> 4;
    float acc[8][4];
#pragma unroll
    for (int j=0;j<8;j++)
#pragma unroll
        for (int jj=0;jj<4;jj++) acc[j][jj] = 0.0f;
    for (int kb=0; kb<4; kb++){
        __syncthreads();
        for (int e=tid; e<4096; e+=256){
            int cc = e>>5, kk = e&31;
            ws[kk][cc] = w[cc*128 + kb*32 + kk];
        }
        __syncthreads();
#pragma unroll 4
        for (int kk=0; kk<32; kk++){
            float4 xv = *(const float4*)&in_s[kb*32+kk][tx*4];
            float4 wa = *(const float4*)&ws[kk][ty*8];
            float4 wb = *(const float4*)&ws[kk][ty*8+4];
            float wv[8] = {wa.x,wa.y,wa.z,wa.w,wb.x,wb.y,wb.z,wb.w};
#pragma unroll
            for (int j=0;j<8;j++){
                acc[j][0] = fmaf(wv[j], xv.x, acc[j][0]);
                acc[j][1] = fmaf(wv[j], xv.y, acc[j][1]);
                acc[j][2] = fmaf(wv[j], xv.z, acc[j][2]);
                acc[j][3] = fmaf(wv[j], xv.w, acc[j][3]);
            }
        }
    }
#pragma unroll
    for (int j=0;j<8;j++){
        int cc = ty*8 + j;
        float bv = bias[cc];
        float* out = g_mid + (size_t)(b*128+cc)*4096 + pt*64 + tx*4;
#pragma unroll
        for (int jj=0;jj<4;jj++) out[jj] = gelu_exact(acc[j][jj] + bv);
    }
}

// ---------------- K9: proj2 (128->256 1x1) ----------------
__global__ __launch_bounds__(256) void proj2_kernel(const float* __restrict__ w,
                                                    const float* __restrict__ bias){
    __shared__ float in_s[128][64];
    __shared__ float ws[32][128];
    int pt = blockIdx.x, b = blockIdx.y;
    int tid = threadIdx.x;
    for (int e=tid; e<8192; e+=256){
        int cc = e>>6, p = e&63;
        in_s[cc][p] = g_mid[(size_t)(b*128+cc)*4096 + pt*64 + p];
    }
    int tx = tid & 15, ty = tid >> 4;
    for (int och=0; och<2; och++){
        float acc[8][4];
#pragma unroll
        for (int j=0;j<8;j++)
#pragma unroll
            for (int jj=0;jj<4;jj++) acc[j][jj] = 0.0f;
        for (int kb=0; kb<4; kb++){
            __syncthreads();
            for (int e=tid; e<4096; e+=256){
                int cc = e>>5, kk = e&31;
                ws[kk][cc] = w[(och*128+cc)*128 + kb*32 + kk];
            }
            __syncthreads();
#pragma unroll 4
            for (int kk=0; kk<32; kk++){
                float4 xv = *(const float4*)&in_s[kb*32+kk][tx*4];
                float4 wa = *(const float4*)&ws[kk][ty*8];
                float4 wb = *(const float4*)&ws[kk][ty*8+4];
                float wv[8] = {wa.x,wa.y,wa.z,wa.w,wb.x,wb.y,wb.z,wb.w};
#pragma unroll
                for (int j=0;j<8;j++){
                    acc[j][0] = fmaf(wv[j], xv.x, acc[j][0]);
                    acc[j][1] = fmaf(wv[j], xv.y, acc[j][1]);
                    acc[j][2] = fmaf(wv[j], xv.z, acc[j][2]);
                    acc[j][3] = fmaf(wv[j], xv.w, acc[j][3]);
                }
            }
        }
#pragma unroll
        for (int j=0;j<8;j++){
            int o = och*128 + ty*8 + j;
            float bv = bias[o];
            float* out = g_proj + (size_t)(b*256+o)*4096 + pt*64 + tx*4;
#pragma unroll
            for (int jj=0;jj<4;jj++) out[jj] = acc[j][jj] + bv;
        }
    }
}

// ---------------- K10: shortcut 4x4-s4 conv (the big GEMM) ----------------
__global__ __launch_bounds__(256) void sc_kernel(const float* __restrict__ x,
                                                 const float* __restrict__ w,
                                                 const float* __restrict__ cb){
    __shared__ float xs[4][4][64];     // [ky][kx][ow]
    __shared__ float Ws[16][68];       // [t][o], padded
    int ob = blockIdx.x, oh = blockIdx.y, b = blockIdx.z;
    int tid = threadIdx.x;
    int tx = tid & 15, ty = tid >> 4;
    float acc[4][4];
#pragma unroll
    for (int i=0;i<4;i++)
#pragma unroll
        for (int j=0;j<4;j++) acc[i][j] = 0.0f;

    int wo = tid >> 2, wt4 = (tid & 3)*4;
    for (int c=0; c<128; c++){
        __syncthreads();
        {
            const float* xrow = x + ((size_t)(b*128+c)*256 + oh*4)*256;
#pragma unroll
            for (int r=0;r<4;r++){
                float v = xrow[r*256 + tid];
                xs[r][tid&3][tid>>2] = v;
            }
            float4 wf = *(const float4*)&w[((size_t)(ob*64+wo)*128 + c)*16 + wt4];
            Ws[wt4+0][wo] = wf.x; Ws[wt4+1][wo] = wf.y;
            Ws[wt4+2][wo] = wf.z; Ws[wt4+3][wo] = wf.w;
        }
        __syncthreads();
#pragma unroll
        for (int ky=0;ky<4;ky++)
#pragma unroll
            for (int kx=0;kx<4;kx++){
                int t = ky*4 + kx;
                float4 wv = *(const float4*)&Ws[t][ty*4];
                float4 xv = *(const float4*)&xs[ky][kx][tx*4];
                acc[0][0]=fmaf(wv.x,xv.x,acc[0][0]); acc[0][1]=fmaf(wv.x,xv.y,acc[0][1]);
                acc[0][2]=fmaf(wv.x,xv.z,acc[0][2]); acc[0][3]=fmaf(wv.x,xv.w,acc[0][3]);
                acc[1][0]=fmaf(wv.y,xv.x,acc[1][0]); acc[1][1]=fmaf(wv.y,xv.y,acc[1][1]);
                acc[1][2]=fmaf(wv.y,xv.z,acc[1][2]); acc[1][3]=fmaf(wv.y,xv.w,acc[1][3]);
                acc[2][0]=fmaf(wv.z,xv.x,acc[2][0]); acc[2][1]=fmaf(wv.z,xv.y,acc[2][1]);
                acc[2][2]=fmaf(wv.z,xv.z,acc[2][2]); acc[2][3]=fmaf(wv.z,xv.w,acc[2][3]);
                acc[3][0]=fmaf(wv.w,xv.x,acc[3][0]); acc[3][1]=fmaf(wv.w,xv.y,acc[3][1]);
                acc[3][2]=fmaf(wv.w,xv.z,acc[3][2]); acc[3][3]=fmaf(wv.w,xv.w,acc[3][3]);
            }
    }
#pragma unroll
    for (int i=0;i<4;i++){
        int o = ob*64 + ty*4 + i;
        float bv = cb[o];
        float* out = g_scv + (size_t)(b*256+o)*4096 + oh*64 + tx*4;
        *(float4*)out = make_float4(acc[i][0]+bv, acc[i][1]+bv, acc[i][2]+bv, acc[i][3]+bv);
    }
}

// ---------------- K11a: per-column LN stats for proj & sc ----------------
__global__ void stats_kernel(){
    int pos = blockIdx.x*256 + threadIdx.x;
    int b = blockIdx.y;
    const float* p1 = g_proj + (size_t)b*256*4096 + pos;
    const float* p2 = g_scv  + (size_t)b*256*4096 + pos;
    float s1=0.f,q1=0.f,s2=0.f,q2=0.f;
    for (int ch=0; ch<256; ch++){
        float v1 = p1[(size_t)ch*4096];
        float v2 = p2[(size_t)ch*4096];
        s1 += v1; q1 = fmaf(v1,v1,q1);
        s2 += v2; q2 = fmaf(v2,v2,q2);
    }
    float mu1 = s1*(1.0f/256.0f), mu2 = s2*(1.0f/256.0f);
    float r1 = rsqrtf(fmaxf(q1*(1.0f/256.0f) - mu1*mu1, 0.0f) + 1e-5f);
    float r2 = rsqrtf(fmaxf(q2*(1.0f/256.0f) - mu2*mu2, 0.0f) + 1e-5f);
    float4* st = (float4*)g_stats;
    st[(size_t)b*4096 + pos] = make_float4(mu1, r1, mu2, r2);
}

// ---------------- K11b: apply both LNs, write tuple element 0 ----------------
__global__ void apply_kernel(float* __restrict__ out,
                             const float* __restrict__ g1, const float* __restrict__ be1,
                             const float* __restrict__ g2, const float* __restrict__ be2){
    size_t idx = (size_t)blockIdx.x*256 + threadIdx.x;
    int pos = (int)(idx & 4095);
    int bo  = (int)(idx >> 12);
    int o = bo & 255, b = bo >> 8;
    float4 st = ((const float4*)g_stats)[(size_t)b*4096 + pos];
    float v1 = g_proj[idx], v2 = g_scv[idx];
    out[idx] = (v1 - st.x)*st.y*g1[o] + be1[o] + (v2 - st.z)*st.w*g2[o] + be2[o];
}

// ---------------- launch ----------------
extern "C" void kernel_launch(void* const* d_in, const int* in_sizes, int n_in,
                              void* d_out, int out_size){
    const float* x    = (const float*)d_in[0];
    const float* q_w  = (const float*)d_in[1];
    const float* q_b  = (const float*)d_in[2];
    const float* k_w  = (const float*)d_in[3];
    const float* k_b  = (const float*)d_in[4];
    const float* v_w  = (const float*)d_in[5];
    const float* v_b  = (const float*)d_in[6];
    const float* qp_w = (const float*)d_in[7];
    const float* qp_b = (const float*)d_in[8];
    const float* kp_w = (const float*)d_in[9];
    const float* kp_b = (const float*)d_in[10];
    const float* vp_w = (const float*)d_in[11];
    const float* vp_b = (const float*)d_in[12];
    const float* lscale = (const float*)d_in[13];
    const float* cpb_w1 = (const float*)d_in[14];
    const float* cpb_b1 = (const float*)d_in[15];
    const float* cpb_w2 = (const float*)d_in[16];
    const float* pw1 = (const float*)d_in[17];
    const float* pb1 = (const float*)d_in[18];
    const float* pw2 = (const float*)d_in[19];
    const float* pb2 = (const float*)d_in[20];
    const float* ng  = (const float*)d_in[21];
    const float* nbe = (const float*)d_in[22];
    const float* sc_w  = (const float*)d_in[23];
    const float* sc_cb = (const float*)d_in[24];
    const float* sc_g  = (const float*)d_in[25];
    const float* sc_be = (const float*)d_in[26];
    float* out = (float*)d_out;

    cudaMemcpyAsync(out + OUT0_ELEMS, x, (size_t)X_ELEMS*sizeof(float),
                    cudaMemcpyDeviceToDevice, 0);
    bias_kernel<<<64, 256>>>(cpb_w1, cpb_b1, cpb_w2);
    qkv_kernel<<<dim3(256,32), 256>>>(x, q_w,q_b, k_w,k_b, v_w,v_b, vp_w,vp_b);
    dw3_kernel<<<1024, 256>>>(qp_w, qp_b, kp_w, kp_b);
    norm_kernel<<<32, 256>>>();
    sim_kernel<<<64, 256>>>(lscale);
    softmax_kernel<<<512, 256>>>();
    attn_kernel<<<dim3(16,4,8), 256>>>();
    proj1_kernel<<<dim3(64,8), 256>>>(pw1, pb1);
    sc_kernel<<<dim3(4,64,8), 256>>>(x, sc_w, sc_cb);
    proj2_kernel<<<dim3(64,8), 256>>>(pw2, pb2);
    stats_kernel<<<dim3(16,8), 256>>>();
    apply_kernel<<<OUT0_ELEMS/256, 256>>>(out, ng, nbe, sc_g, sc_be);
}